// round 3
// baseline (speedup 1.0000x reference)
#include <cuda_runtime.h>
#include <cuda_bf16.h>

// ---------------------------------------------------------------------------
// CausalSelfAttention  (B=4, T=2048, DIM=1024, H=16, Dh=64), fp32
//   1) QKV projections:  q/k/v = x @ W^T  (fused kernel, blockIdx.z picks W)
//   2) causal flash attention per (b, h, q-tile)
//   3) output projection: out = att @ wo^T
// Double-buffered SGEMM mainloop; shuffle-based online softmax.
// Scratch in __device__ globals; graph-capturable; no allocations.
// ---------------------------------------------------------------------------

#define BATCH 4
#define SEQ   2048
#define DIM   1024
#define NHEAD 16
#define HDIM  64
#define MROWS (BATCH * SEQ)   // 8192

__device__ float g_q[MROWS * DIM];
__device__ float g_k[MROWS * DIM];
__device__ float g_v[MROWS * DIM];
__device__ float g_att[MROWS * DIM];

// ---------------------------------------------------------------------------
// SGEMM:  C[m,n] = sum_k A[m,k] * B[n,k]   (A: MxK row-major, B: NxK row-major)
// 128x128 tile, Ktile=8, 256 threads, 8x8 microtile, 2-stage smem pipeline.
// ---------------------------------------------------------------------------
#define GT 128
#define GK 8
#define GPAD 132   // row stride in floats (multiple of 4 -> float4-aligned)

__device__ __forceinline__ void sgemm_nt_body(
    const float* __restrict__ A, const float* __restrict__ B,
    float* __restrict__ C, int N, int K,
    int m0, int n0)
{
    __shared__ float As[2][GK][GPAD];
    __shared__ float Bs[2][GK][GPAD];

    const int tid = threadIdx.x;
    const int lr  = tid >> 1;          // 0..127 (tile row loaded by this thread)
    const int lc  = (tid & 1) * 4;     // 0 or 4 (k offset)
    const int ty  = tid >> 4;          // 0..15
    const int tx  = tid & 15;          // 0..15

    float acc[8][8];
#pragma unroll
    for (int i = 0; i < 8; i++)
#pragma unroll
        for (int j = 0; j < 8; j++) acc[i][j] = 0.f;

    const float* Aptr = A + (long)(m0 + lr) * K + lc;
    const float* Bptr = B + (long)(n0 + lr) * K + lc;

    // Prologue: load tile 0 into buffer 0
    float4 av = *(const float4*)(Aptr);
    float4 bv = *(const float4*)(Bptr);
    As[0][lc + 0][lr] = av.x; As[0][lc + 1][lr] = av.y;
    As[0][lc + 2][lr] = av.z; As[0][lc + 3][lr] = av.w;
    Bs[0][lc + 0][lr] = bv.x; Bs[0][lc + 1][lr] = bv.y;
    Bs[0][lc + 2][lr] = bv.z; Bs[0][lc + 3][lr] = bv.w;
    __syncthreads();

    int buf = 0;
    for (int kt = 0; kt < K; kt += GK) {
        // Prefetch next tile into registers (overlaps with FMA below)
        const bool have_next = (kt + GK) < K;
        float4 anext, bnext;
        if (have_next) {
            anext = *(const float4*)(Aptr + kt + GK);
            bnext = *(const float4*)(Bptr + kt + GK);
        }

#pragma unroll
        for (int kk = 0; kk < GK; kk++) {
            float a[8], b[8];
            *(float4*)(&a[0]) = *(const float4*)(&As[buf][kk][ty * 8]);
            *(float4*)(&a[4]) = *(const float4*)(&As[buf][kk][ty * 8 + 4]);
            *(float4*)(&b[0]) = *(const float4*)(&Bs[buf][kk][tx * 8]);
            *(float4*)(&b[4]) = *(const float4*)(&Bs[buf][kk][tx * 8 + 4]);
#pragma unroll
            for (int i = 0; i < 8; i++)
#pragma unroll
                for (int j = 0; j < 8; j++)
                    acc[i][j] += a[i] * b[j];
        }

        if (have_next) {
            const int nb = buf ^ 1;
            As[nb][lc + 0][lr] = anext.x; As[nb][lc + 1][lr] = anext.y;
            As[nb][lc + 2][lr] = anext.z; As[nb][lc + 3][lr] = anext.w;
            Bs[nb][lc + 0][lr] = bnext.x; Bs[nb][lc + 1][lr] = bnext.y;
            Bs[nb][lc + 2][lr] = bnext.z; Bs[nb][lc + 3][lr] = bnext.w;
            __syncthreads();
            buf = nb;
        }
    }

#pragma unroll
    for (int i = 0; i < 8; i++) {
        long row = m0 + ty * 8 + i;
        float4 v0 = make_float4(acc[i][0], acc[i][1], acc[i][2], acc[i][3]);
        float4 v1 = make_float4(acc[i][4], acc[i][5], acc[i][6], acc[i][7]);
        *(float4*)(&C[row * N + n0 + tx * 8 + 0]) = v0;
        *(float4*)(&C[row * N + n0 + tx * 8 + 4]) = v1;
    }
}

// Fused QKV projection: blockIdx.z selects weight and destination.
__global__ __launch_bounds__(256) void qkv_gemm_kernel(
    const float* __restrict__ x,
    const float* __restrict__ wq,
    const float* __restrict__ wk,
    const float* __restrict__ wv)
{
    const int z = blockIdx.z;
    const float* W = (z == 0) ? wq : (z == 1) ? wk : wv;
    float* dst     = (z == 0) ? g_q : (z == 1) ? g_k : g_v;
    sgemm_nt_body(x, W, dst, DIM, DIM, blockIdx.y * GT, blockIdx.x * GT);
}

// Output projection: out = g_att @ wo^T
__global__ __launch_bounds__(256) void out_gemm_kernel(
    const float* __restrict__ wo, float* __restrict__ out)
{
    sgemm_nt_body(g_att, wo, out, DIM, DIM, blockIdx.y * GT, blockIdx.x * GT);
}

// ---------------------------------------------------------------------------
// Flash attention (causal).  One block = 64 query rows of one (b, h).
// BK = 32 key columns per inner tile. 256 threads (16x16).
// Online softmax: 2 lanes per row (lane pair 2r, 2r+1 of warps 0..3),
// combined with __shfl_xor_sync — no smem scratch, no fences.
// ---------------------------------------------------------------------------
#define BQ 64
#define BK 32

__global__ __launch_bounds__(256) void attn_kernel()
{
    __shared__ float Qs[BQ][HDIM + 1];   // 64x65
    __shared__ float Ks[BK][HDIM + 1];   // 32x65
    __shared__ float Vs[BK][HDIM + 4];   // 32x68 (float4-aligned rows)
    __shared__ float Ss[BQ][BK + 1];     // 64x33
    __shared__ float m_s[BQ], l_s[BQ], alf[BQ];

    const int tid = threadIdx.x;
    const int tx  = tid & 15;    // 0..15
    const int ty  = tid >> 4;    // 0..15
    const int q0  = blockIdx.x * BQ;
    const int h   = blockIdx.y;
    const int b   = blockIdx.z;
    const long base = (long)b * SEQ;      // row offset into [MROWS, DIM]
    const int  hoff = h * HDIM;

    // Load Q tile (scaled by 1/sqrt(Dh) = 0.125)
    {
        int row = tid >> 2;            // 0..63
        int col = (tid & 3) * 16;      // 0,16,32,48
        const float* src = &g_q[(base + q0 + row) * DIM + hoff + col];
#pragma unroll
        for (int i = 0; i < 16; i += 4) {
            float4 v = *(const float4*)(src + i);
            Qs[row][col + i + 0] = v.x * 0.125f;
            Qs[row][col + i + 1] = v.y * 0.125f;
            Qs[row][col + i + 2] = v.z * 0.125f;
            Qs[row][col + i + 3] = v.w * 0.125f;
        }
    }
    if (tid < BQ) { m_s[tid] = -1e30f; l_s[tid] = 0.f; }

    float o[4][4];
#pragma unroll
    for (int i = 0; i < 4; i++)
#pragma unroll
        for (int j = 0; j < 4; j++) o[i][j] = 0.f;

    const int nkt = (q0 + BQ) / BK;   // number of key tiles (causal)
    for (int kt = 0; kt < nkt; kt++) {
        const int k0 = kt * BK;

        // Load K and V tiles (32x64 each)
        {
            int row = tid >> 3;            // 0..31
            int col = (tid & 7) * 8;       // 0..56
            const float* ksrc = &g_k[(base + k0 + row) * DIM + hoff + col];
            const float* vsrc = &g_v[(base + k0 + row) * DIM + hoff + col];
#pragma unroll
            for (int i = 0; i < 8; i += 4) {
                float4 kv = *(const float4*)(ksrc + i);
                float4 vv = *(const float4*)(vsrc + i);
                Ks[row][col + i + 0] = kv.x; Ks[row][col + i + 1] = kv.y;
                Ks[row][col + i + 2] = kv.z; Ks[row][col + i + 3] = kv.w;
                Vs[row][col + i + 0] = vv.x; Vs[row][col + i + 1] = vv.y;
                Vs[row][col + i + 2] = vv.z; Vs[row][col + i + 3] = vv.w;
            }
        }
        __syncthreads();

        // S = Q * K^T : each thread computes 4 rows x 2 cols
        {
            float s[4][2];
#pragma unroll
            for (int i = 0; i < 4; i++) { s[i][0] = 0.f; s[i][1] = 0.f; }
            const int c0 = tx * 2;
#pragma unroll 8
            for (int d = 0; d < HDIM; d++) {
                float b0 = Ks[c0 + 0][d];
                float b1 = Ks[c0 + 1][d];
#pragma unroll
                for (int i = 0; i < 4; i++) {
                    float a = Qs[ty * 4 + i][d];
                    s[i][0] += a * b0;
                    s[i][1] += a * b1;
                }
            }
            const bool boundary = (k0 + BK - 1 > q0);
#pragma unroll
            for (int i = 0; i < 4; i++) {
                int row = ty * 4 + i;
#pragma unroll
                for (int j = 0; j < 2; j++) {
                    float v = s[i][j];
                    if (boundary && (k0 + c0 + j > q0 + row)) v = -1e30f;
                    Ss[row][c0 + j] = v;
                }
            }
        }
        __syncthreads();

        // Online softmax: 2 lanes per row, combined via shuffle.
        // tid in [0, 128): row = tid>>1 (lanes 2r, 2r+1 are warp-adjacent).
        if (tid < BQ * 2) {
            const int row  = tid >> 1;
            const int cbeg = (tid & 1) * (BK / 2);
            const float mo = m_s[row];

            float mx = -1e30f;
#pragma unroll
            for (int c = 0; c < BK / 2; c++) mx = fmaxf(mx, Ss[row][cbeg + c]);
            mx = fmaxf(mx, __shfl_xor_sync(0xFFFFFFFFu, mx, 1));
            mx = fmaxf(mx, mo);                       // row max incl. history

            float sum = 0.f;
#pragma unroll
            for (int c = 0; c < BK / 2; c++) {
                float p = __expf(Ss[row][cbeg + c] - mx);
                Ss[row][cbeg + c] = p;
                sum += p;
            }
            sum += __shfl_xor_sync(0xFFFFFFFFu, sum, 1);

            if ((tid & 1) == 0) {
                float a = __expf(mo - mx);
                m_s[row] = mx;
                l_s[row] = l_s[row] * a + sum;
                alf[row] = a;
            }
        }
        __syncthreads();

        // O = O*alpha + P @ V : each thread owns rows ty*4.., cols tx*4..
        {
            const int c0 = tx * 4;
#pragma unroll
            for (int i = 0; i < 4; i++) {
                const int row = ty * 4 + i;
                const float a = alf[row];
                float o0 = o[i][0] * a, o1 = o[i][1] * a;
                float o2 = o[i][2] * a, o3 = o[i][3] * a;
#pragma unroll 8
                for (int j = 0; j < BK; j++) {
                    float p = Ss[row][j];
                    float4 v = *(const float4*)(&Vs[j][c0]);
                    o0 += p * v.x; o1 += p * v.y;
                    o2 += p * v.z; o3 += p * v.w;
                }
                o[i][0] = o0; o[i][1] = o1; o[i][2] = o2; o[i][3] = o3;
            }
        }
        __syncthreads();
    }

    // Epilogue: divide by l, write to g_att in [B*T, DIM] layout
#pragma unroll
    for (int i = 0; i < 4; i++) {
        const int row = ty * 4 + i;
        const float inv = 1.0f / l_s[row];
        float4 v = make_float4(o[i][0] * inv, o[i][1] * inv,
                               o[i][2] * inv, o[i][3] * inv);
        *(float4*)(&g_att[(base + q0 + row) * DIM + hoff + tx * 4]) = v;
    }
}

// ---------------------------------------------------------------------------
extern "C" void kernel_launch(void* const* d_in, const int* in_sizes, int n_in,
                              void* d_out, int out_size)
{
    const float* x  = (const float*)d_in[0];
    const float* wq = (const float*)d_in[1];
    const float* wk = (const float*)d_in[2];
    const float* wv = (const float*)d_in[3];
    const float* wo = (const float*)d_in[4];
    float* out = (float*)d_out;

    dim3 gqkv(DIM / GT, MROWS / GT, 3);       // (8, 64, 3)
    qkv_gemm_kernel<<<gqkv, 256>>>(x, wq, wk, wv);

    dim3 gattn(SEQ / BQ, NHEAD, BATCH);        // (32, 16, 4)
    attn_kernel<<<gattn, 256>>>();

    dim3 gout(DIM / GT, MROWS / GT);           // (8, 64)
    out_gemm_kernel<<<gout, 256>>>(wo, out);
}

// round 13
// speedup vs baseline: 1.0817x; 1.0817x over previous
#include <cuda_runtime.h>
#include <cuda_bf16.h>

// ---------------------------------------------------------------------------
// CausalSelfAttention  (B=4, T=2048, DIM=1024, H=16, Dh=64)
//   1) QKV projections  q/k/v = x @ W^T   — 3xTF32 tensor-core GEMM
//   2) causal flash attention (fp32, unchanged from passing round-3 kernel)
//   3) output projection out = att @ wo^T — 3xTF32 tensor-core GEMM
// 3xTF32: a = tf32(a) + tf32(a - tf32(a)); D += Ah*Bh + Ah*Bl + Al*Bh.
// Near-fp32 accuracy, tensor-pipe throughput.
// Scratch in __device__ globals; graph-capturable; no allocations.
// ---------------------------------------------------------------------------

#define BATCH 4
#define SEQ   2048
#define DIM   1024
#define NHEAD 16
#define HDIM  64
#define MROWS (BATCH * SEQ)   // 8192

__device__ float g_q[MROWS * DIM];
__device__ float g_k[MROWS * DIM];
__device__ float g_v[MROWS * DIM];
__device__ float g_att[MROWS * DIM];

// ---------------------------------------------------------------------------
// 3xTF32 GEMM:  C[m,n] = sum_k A[m,k] * B[n,k]
// 128x128 CTA tile, Ktile=8, 256 threads (8 warps as 2x4, warp tile 64x32).
// Double-buffered smem with hi/lo tf32 planes, stride 136 (conflict-free
// fragment loads: bank = (8k + m) & 31 is injective over a warp).
// ---------------------------------------------------------------------------
#define GT   128
#define KT   8
#define SSTR 136

__device__ __forceinline__ unsigned tf32_of(float x) {
    unsigned u;
    asm("cvt.rna.tf32.f32 %0, %1;" : "=r"(u) : "f"(x));
    return u;
}

__device__ __forceinline__ void mma_tf32(float c[4], const unsigned a[4],
                                         const unsigned b[2]) {
    asm volatile(
        "mma.sync.aligned.m16n8k8.row.col.f32.tf32.tf32.f32 "
        "{%0,%1,%2,%3}, {%4,%5,%6,%7}, {%8,%9}, {%0,%1,%2,%3};\n"
        : "+f"(c[0]), "+f"(c[1]), "+f"(c[2]), "+f"(c[3])
        : "r"(a[0]), "r"(a[1]), "r"(a[2]), "r"(a[3]),
          "r"(b[0]), "r"(b[1]));
}

__device__ __forceinline__ void stage_decomp(
    unsigned (*H)[SSTR], unsigned (*L)[SSTR], float4 v, int lr, int lc)
{
    float a[4] = {v.x, v.y, v.z, v.w};
#pragma unroll
    for (int j = 0; j < 4; j++) {
        unsigned hi = tf32_of(a[j]);
        float lo = a[j] - __uint_as_float(hi);   // exact in fp32
        H[lc + j][lr] = hi;
        L[lc + j][lr] = tf32_of(lo);
    }
}

__device__ __forceinline__ void gemm3tf32_body(
    const float* __restrict__ A, const float* __restrict__ B,
    float* __restrict__ C, int N, int K, int m0, int n0)
{
    __shared__ unsigned AsH[2][KT][SSTR], AsL[2][KT][SSTR];
    __shared__ unsigned BsH[2][KT][SSTR], BsL[2][KT][SSTR];

    const int tid  = threadIdx.x;
    const int lane = tid & 31;
    const int wid  = tid >> 5;
    const int wm   = wid >> 2;   // 0..1 : warp row   (64 rows each)
    const int wn   = wid & 3;    // 0..3 : warp col   (32 cols each)

    const int lr = tid >> 1;         // 0..127: staged row of A/B tile
    const int lc = (tid & 1) * 4;    // 0 or 4: staged k offset

    float c[4][4][4];
#pragma unroll
    for (int t = 0; t < 4; t++)
#pragma unroll
        for (int u = 0; u < 4; u++)
#pragma unroll
            for (int r = 0; r < 4; r++) c[t][u][r] = 0.f;

    const float* Aptr = A + (long)(m0 + lr) * K + lc;
    const float* Bptr = B + (long)(n0 + lr) * K + lc;

    // Prologue: stage tile 0 into buffer 0
    {
        float4 av = *(const float4*)(Aptr);
        float4 bv = *(const float4*)(Bptr);
        stage_decomp(AsH[0], AsL[0], av, lr, lc);
        stage_decomp(BsH[0], BsL[0], bv, lr, lc);
    }
    __syncthreads();

    const int kk = lane & 3;     // k index within frag
    const int qq = lane >> 2;    // row/col group within frag

    int buf = 0;
    for (int kt = 0; kt < K; kt += KT) {
        const bool have_next = (kt + KT) < K;
        float4 av, bv;
        if (have_next) {
            av = *(const float4*)(Aptr + kt + KT);
            bv = *(const float4*)(Bptr + kt + KT);
        }

        // Load fragments (hi + lo)
        unsigned ah[4][4], al[4][4], bh[4][2], bl[4][2];
#pragma unroll
        for (int t = 0; t < 4; t++) {
            const int m = wm * 64 + t * 16 + qq;
            ah[t][0] = AsH[buf][kk][m];     ah[t][1] = AsH[buf][kk][m + 8];
            ah[t][2] = AsH[buf][kk + 4][m]; ah[t][3] = AsH[buf][kk + 4][m + 8];
            al[t][0] = AsL[buf][kk][m];     al[t][1] = AsL[buf][kk][m + 8];
            al[t][2] = AsL[buf][kk + 4][m]; al[t][3] = AsL[buf][kk + 4][m + 8];
        }
#pragma unroll
        for (int u = 0; u < 4; u++) {
            const int n = wn * 32 + u * 8 + qq;
            bh[u][0] = BsH[buf][kk][n];     bh[u][1] = BsH[buf][kk + 4][n];
            bl[u][0] = BsL[buf][kk][n];     bl[u][1] = BsL[buf][kk + 4][n];
        }

        // 3xTF32 MMA: hi*hi + hi*lo + lo*hi
#pragma unroll
        for (int t = 0; t < 4; t++)
#pragma unroll
            for (int u = 0; u < 4; u++) {
                mma_tf32(c[t][u], ah[t], bh[u]);
                mma_tf32(c[t][u], ah[t], bl[u]);
                mma_tf32(c[t][u], al[t], bh[u]);
            }

        if (have_next) {
            const int nb = buf ^ 1;
            stage_decomp(AsH[nb], AsL[nb], av, lr, lc);
            stage_decomp(BsH[nb], BsL[nb], bv, lr, lc);
            __syncthreads();
            buf = nb;
        }
    }

    // Epilogue: c0,c1 -> (row, 2tg), (row, 2tg+1); c2,c3 -> row+8
    const int p2 = (lane & 3) * 2;
#pragma unroll
    for (int t = 0; t < 4; t++) {
        const long r = m0 + wm * 64 + t * 16 + qq;
#pragma unroll
        for (int u = 0; u < 4; u++) {
            const int cc = n0 + wn * 32 + u * 8 + p2;
            *(float2*)(&C[r * N + cc])       = make_float2(c[t][u][0], c[t][u][1]);
            *(float2*)(&C[(r + 8) * N + cc]) = make_float2(c[t][u][2], c[t][u][3]);
        }
    }
}

// Fused QKV projection: blockIdx.z selects weight and destination.
__global__ __launch_bounds__(256) void qkv_gemm_kernel(
    const float* __restrict__ x,
    const float* __restrict__ wq,
    const float* __restrict__ wk,
    const float* __restrict__ wv)
{
    const int z = blockIdx.z;
    const float* W = (z == 0) ? wq : (z == 1) ? wk : wv;
    float* dst     = (z == 0) ? g_q : (z == 1) ? g_k : g_v;
    gemm3tf32_body(x, W, dst, DIM, DIM, blockIdx.y * GT, blockIdx.x * GT);
}

// Output projection: out = g_att @ wo^T
__global__ __launch_bounds__(256) void out_gemm_kernel(
    const float* __restrict__ wo, float* __restrict__ out)
{
    gemm3tf32_body(g_att, wo, out, DIM, DIM, blockIdx.y * GT, blockIdx.x * GT);
}

// ---------------------------------------------------------------------------
// Flash attention (causal) — unchanged from passing round-3 kernel.
// One block = 64 query rows of one (b, h). BK = 32. 256 threads (16x16).
// ---------------------------------------------------------------------------
#define BQ 64
#define BK 32

__global__ __launch_bounds__(256) void attn_kernel()
{
    __shared__ float Qs[BQ][HDIM + 1];   // 64x65
    __shared__ float Ks[BK][HDIM + 1];   // 32x65
    __shared__ float Vs[BK][HDIM + 4];   // 32x68 (float4-aligned rows)
    __shared__ float Ss[BQ][BK + 1];     // 64x33
    __shared__ float m_s[BQ], l_s[BQ], alf[BQ];

    const int tid = threadIdx.x;
    const int tx  = tid & 15;    // 0..15
    const int ty  = tid >> 4;    // 0..15
    const int q0  = blockIdx.x * BQ;
    const int h   = blockIdx.y;
    const int b   = blockIdx.z;
    const long base = (long)b * SEQ;
    const int  hoff = h * HDIM;

    // Load Q tile (scaled by 1/sqrt(Dh) = 0.125)
    {
        int row = tid >> 2;            // 0..63
        int col = (tid & 3) * 16;      // 0,16,32,48
        const float* src = &g_q[(base + q0 + row) * DIM + hoff + col];
#pragma unroll
        for (int i = 0; i < 16; i += 4) {
            float4 v = *(const float4*)(src + i);
            Qs[row][col + i + 0] = v.x * 0.125f;
            Qs[row][col + i + 1] = v.y * 0.125f;
            Qs[row][col + i + 2] = v.z * 0.125f;
            Qs[row][col + i + 3] = v.w * 0.125f;
        }
    }
    if (tid < BQ) { m_s[tid] = -1e30f; l_s[tid] = 0.f; }

    float o[4][4];
#pragma unroll
    for (int i = 0; i < 4; i++)
#pragma unroll
        for (int j = 0; j < 4; j++) o[i][j] = 0.f;

    const int nkt = (q0 + BQ) / BK;   // number of key tiles (causal)
    for (int kt = 0; kt < nkt; kt++) {
        const int k0 = kt * BK;

        // Load K and V tiles (32x64 each)
        {
            int row = tid >> 3;            // 0..31
            int col = (tid & 7) * 8;       // 0..56
            const float* ksrc = &g_k[(base + k0 + row) * DIM + hoff + col];
            const float* vsrc = &g_v[(base + k0 + row) * DIM + hoff + col];
#pragma unroll
            for (int i = 0; i < 8; i += 4) {
                float4 kv = *(const float4*)(ksrc + i);
                float4 vv = *(const float4*)(vsrc + i);
                Ks[row][col + i + 0] = kv.x; Ks[row][col + i + 1] = kv.y;
                Ks[row][col + i + 2] = kv.z; Ks[row][col + i + 3] = kv.w;
                Vs[row][col + i + 0] = vv.x; Vs[row][col + i + 1] = vv.y;
                Vs[row][col + i + 2] = vv.z; Vs[row][col + i + 3] = vv.w;
            }
        }
        __syncthreads();

        // S = Q * K^T : each thread computes 4 rows x 2 cols
        {
            float s[4][2];
#pragma unroll
            for (int i = 0; i < 4; i++) { s[i][0] = 0.f; s[i][1] = 0.f; }
            const int c0 = tx * 2;
#pragma unroll 8
            for (int d = 0; d < HDIM; d++) {
                float b0 = Ks[c0 + 0][d];
                float b1 = Ks[c0 + 1][d];
#pragma unroll
                for (int i = 0; i < 4; i++) {
                    float a = Qs[ty * 4 + i][d];
                    s[i][0] += a * b0;
                    s[i][1] += a * b1;
                }
            }
            const bool boundary = (k0 + BK - 1 > q0);
#pragma unroll
            for (int i = 0; i < 4; i++) {
                int row = ty * 4 + i;
#pragma unroll
                for (int j = 0; j < 2; j++) {
                    float v = s[i][j];
                    if (boundary && (k0 + c0 + j > q0 + row)) v = -1e30f;
                    Ss[row][c0 + j] = v;
                }
            }
        }
        __syncthreads();

        // Online softmax: 2 lanes per row, combined via shuffle.
        if (tid < BQ * 2) {
            const int row  = tid >> 1;
            const int cbeg = (tid & 1) * (BK / 2);
            const float mo = m_s[row];

            float mx = -1e30f;
#pragma unroll
            for (int c = 0; c < BK / 2; c++) mx = fmaxf(mx, Ss[row][cbeg + c]);
            mx = fmaxf(mx, __shfl_xor_sync(0xFFFFFFFFu, mx, 1));
            mx = fmaxf(mx, mo);

            float sum = 0.f;
#pragma unroll
            for (int c = 0; c < BK / 2; c++) {
                float p = __expf(Ss[row][cbeg + c] - mx);
                Ss[row][cbeg + c] = p;
                sum += p;
            }
            sum += __shfl_xor_sync(0xFFFFFFFFu, sum, 1);

            if ((tid & 1) == 0) {
                float a = __expf(mo - mx);
                m_s[row] = mx;
                l_s[row] = l_s[row] * a + sum;
                alf[row] = a;
            }
        }
        __syncthreads();

        // O = O*alpha + P @ V
        {
            const int c0 = tx * 4;
#pragma unroll
            for (int i = 0; i < 4; i++) {
                const int row = ty * 4 + i;
                const float a = alf[row];
                float o0 = o[i][0] * a, o1 = o[i][1] * a;
                float o2 = o[i][2] * a, o3 = o[i][3] * a;
#pragma unroll 8
                for (int j = 0; j < BK; j++) {
                    float p = Ss[row][j];
                    float4 v = *(const float4*)(&Vs[j][c0]);
                    o0 += p * v.x; o1 += p * v.y;
                    o2 += p * v.z; o3 += p * v.w;
                }
                o[i][0] = o0; o[i][1] = o1; o[i][2] = o2; o[i][3] = o3;
            }
        }
        __syncthreads();
    }

    // Epilogue
#pragma unroll
    for (int i = 0; i < 4; i++) {
        const int row = ty * 4 + i;
        const float inv = 1.0f / l_s[row];
        float4 v = make_float4(o[i][0] * inv, o[i][1] * inv,
                               o[i][2] * inv, o[i][3] * inv);
        *(float4*)(&g_att[(base + q0 + row) * DIM + hoff + tx * 4]) = v;
    }
}

// ---------------------------------------------------------------------------
extern "C" void kernel_launch(void* const* d_in, const int* in_sizes, int n_in,
                              void* d_out, int out_size)
{
    const float* x  = (const float*)d_in[0];
    const float* wq = (const float*)d_in[1];
    const float* wk = (const float*)d_in[2];
    const float* wv = (const float*)d_in[3];
    const float* wo = (const float*)d_in[4];
    float* out = (float*)d_out;

    dim3 gqkv(DIM / GT, MROWS / GT, 3);       // (8, 64, 3)
    qkv_gemm_kernel<<<gqkv, 256>>>(x, wq, wk, wv);

    dim3 gattn(SEQ / BQ, NHEAD, BATCH);        // (32, 16, 4)
    attn_kernel<<<gattn, 256>>>();

    dim3 gout(DIM / GT, MROWS / GT);           // (8, 64)
    out_gemm_kernel<<<gout, 256>>>(wo, out);
}

// round 15
// speedup vs baseline: 1.7165x; 1.5868x over previous
#include <cuda_runtime.h>
#include <cuda_bf16.h>

// ---------------------------------------------------------------------------
// CausalSelfAttention  (B=4, T=2048, DIM=1024, H=16, Dh=64)
//   1) QKV projections  q/k/v = x @ W^T   — 3xTF32 tensor-core GEMM (verified)
//   2) causal flash attention — tensor-core:
//        QK^T: 3xTF32 (Q hi/lo register fragments, K hi/lo smem)
//        softmax: verified fp32 shuffle-pair version (unchanged logic)
//        P·V:  single-tf32 P and V (rna-rounded; error ~3e-4 << 1e-3)
//   3) output projection out = att @ wo^T — 3xTF32 tensor-core GEMM (verified)
// Scratch in __device__ globals; graph-capturable; no allocations.
// ---------------------------------------------------------------------------

#define BATCH 4
#define SEQ   2048
#define DIM   1024
#define NHEAD 16
#define HDIM  64
#define MROWS (BATCH * SEQ)   // 8192

__device__ float g_q[MROWS * DIM];
__device__ float g_k[MROWS * DIM];
__device__ float g_v[MROWS * DIM];
__device__ float g_att[MROWS * DIM];

// ---------------------------------------------------------------------------
// 3xTF32 GEMM (byte-identical to round-13 verified version)
// ---------------------------------------------------------------------------
#define GT   128
#define KT   8
#define SSTR 136

__device__ __forceinline__ unsigned tf32_of(float x) {
    unsigned u;
    asm("cvt.rna.tf32.f32 %0, %1;" : "=r"(u) : "f"(x));
    return u;
}

__device__ __forceinline__ void mma_tf32(float c[4], const unsigned a[4],
                                         const unsigned b[2]) {
    asm volatile(
        "mma.sync.aligned.m16n8k8.row.col.f32.tf32.tf32.f32 "
        "{%0,%1,%2,%3}, {%4,%5,%6,%7}, {%8,%9}, {%0,%1,%2,%3};\n"
        : "+f"(c[0]), "+f"(c[1]), "+f"(c[2]), "+f"(c[3])
        : "r"(a[0]), "r"(a[1]), "r"(a[2]), "r"(a[3]),
          "r"(b[0]), "r"(b[1]));
}

__device__ __forceinline__ void stage_decomp(
    unsigned (*H)[SSTR], unsigned (*L)[SSTR], float4 v, int lr, int lc)
{
    float a[4] = {v.x, v.y, v.z, v.w};
#pragma unroll
    for (int j = 0; j < 4; j++) {
        unsigned hi = tf32_of(a[j]);
        float lo = a[j] - __uint_as_float(hi);   // exact in fp32
        H[lc + j][lr] = hi;
        L[lc + j][lr] = tf32_of(lo);
    }
}

__device__ __forceinline__ void gemm3tf32_body(
    const float* __restrict__ A, const float* __restrict__ B,
    float* __restrict__ C, int N, int K, int m0, int n0)
{
    __shared__ unsigned AsH[2][KT][SSTR], AsL[2][KT][SSTR];
    __shared__ unsigned BsH[2][KT][SSTR], BsL[2][KT][SSTR];

    const int tid  = threadIdx.x;
    const int lane = tid & 31;
    const int wid  = tid >> 5;
    const int wm   = wid >> 2;
    const int wn   = wid & 3;

    const int lr = tid >> 1;
    const int lc = (tid & 1) * 4;

    float c[4][4][4];
#pragma unroll
    for (int t = 0; t < 4; t++)
#pragma unroll
        for (int u = 0; u < 4; u++)
#pragma unroll
            for (int r = 0; r < 4; r++) c[t][u][r] = 0.f;

    const float* Aptr = A + (long)(m0 + lr) * K + lc;
    const float* Bptr = B + (long)(n0 + lr) * K + lc;

    {
        float4 av = *(const float4*)(Aptr);
        float4 bv = *(const float4*)(Bptr);
        stage_decomp(AsH[0], AsL[0], av, lr, lc);
        stage_decomp(BsH[0], BsL[0], bv, lr, lc);
    }
    __syncthreads();

    const int kk = lane & 3;
    const int qq = lane >> 2;

    int buf = 0;
    for (int kt = 0; kt < K; kt += KT) {
        const bool have_next = (kt + KT) < K;
        float4 av, bv;
        if (have_next) {
            av = *(const float4*)(Aptr + kt + KT);
            bv = *(const float4*)(Bptr + kt + KT);
        }

        unsigned ah[4][4], al[4][4], bh[4][2], bl[4][2];
#pragma unroll
        for (int t = 0; t < 4; t++) {
            const int m = wm * 64 + t * 16 + qq;
            ah[t][0] = AsH[buf][kk][m];     ah[t][1] = AsH[buf][kk][m + 8];
            ah[t][2] = AsH[buf][kk + 4][m]; ah[t][3] = AsH[buf][kk + 4][m + 8];
            al[t][0] = AsL[buf][kk][m];     al[t][1] = AsL[buf][kk][m + 8];
            al[t][2] = AsL[buf][kk + 4][m]; al[t][3] = AsL[buf][kk + 4][m + 8];
        }
#pragma unroll
        for (int u = 0; u < 4; u++) {
            const int n = wn * 32 + u * 8 + qq;
            bh[u][0] = BsH[buf][kk][n];     bh[u][1] = BsH[buf][kk + 4][n];
            bl[u][0] = BsL[buf][kk][n];     bl[u][1] = BsL[buf][kk + 4][n];
        }

#pragma unroll
        for (int t = 0; t < 4; t++)
#pragma unroll
            for (int u = 0; u < 4; u++) {
                mma_tf32(c[t][u], ah[t], bh[u]);
                mma_tf32(c[t][u], ah[t], bl[u]);
                mma_tf32(c[t][u], al[t], bh[u]);
            }

        if (have_next) {
            const int nb = buf ^ 1;
            stage_decomp(AsH[nb], AsL[nb], av, lr, lc);
            stage_decomp(BsH[nb], BsL[nb], bv, lr, lc);
            __syncthreads();
            buf = nb;
        }
    }

    const int p2 = (lane & 3) * 2;
#pragma unroll
    for (int t = 0; t < 4; t++) {
        const long r = m0 + wm * 64 + t * 16 + qq;
#pragma unroll
        for (int u = 0; u < 4; u++) {
            const int cc = n0 + wn * 32 + u * 8 + p2;
            *(float2*)(&C[r * N + cc])       = make_float2(c[t][u][0], c[t][u][1]);
            *(float2*)(&C[(r + 8) * N + cc]) = make_float2(c[t][u][2], c[t][u][3]);
        }
    }
}

__global__ __launch_bounds__(256) void qkv_gemm_kernel(
    const float* __restrict__ x,
    const float* __restrict__ wq,
    const float* __restrict__ wk,
    const float* __restrict__ wv)
{
    const int z = blockIdx.z;
    const float* W = (z == 0) ? wq : (z == 1) ? wk : wv;
    float* dst     = (z == 0) ? g_q : (z == 1) ? g_k : g_v;
    gemm3tf32_body(x, W, dst, DIM, DIM, blockIdx.y * GT, blockIdx.x * GT);
}

__global__ __launch_bounds__(256) void out_gemm_kernel(
    const float* __restrict__ wo, float* __restrict__ out)
{
    gemm3tf32_body(g_att, wo, out, DIM, DIM, blockIdx.y * GT, blockIdx.x * GT);
}

// ---------------------------------------------------------------------------
// Tensor-core flash attention (causal).
// Block = 64 q-rows of one (b, h), 256 threads = 8 warps (wr = wid&3 owns 16
// q-rows; wc = wid>>2). BK = 32 keys per tile.
//   QK^T: warp (wr,wc) -> S[16wr.., wc*16..+16), 3xTF32, Q frags in regs.
//   softmax: verified shuffle-pair version on fp32 S in smem.
//   P·V:  warp (wr,wc) -> O[16wr.., wc*32..+32), single-tf32 P and V.
// K planes stride 68 (==4 mod 32): frag loads conflict-free (bank 4qq+kk).
// V stride 68: frag bank 4kk+qq(+8u) — <=2-way. Ss stride 36: A-frag loads
// conflict-free (bank 4qq+kk).
// ---------------------------------------------------------------------------
#define BQ 64
#define BK 32

__global__ __launch_bounds__(256) void attn_kernel()
{
    __shared__ unsigned KsH[BK][68];
    __shared__ unsigned KsL[BK][68];
    __shared__ unsigned Vt[BK][68];
    __shared__ float Ss[BQ][36];
    __shared__ float m_s[BQ], l_s[BQ], alf[BQ];

    const int tid  = threadIdx.x;
    const int lane = tid & 31;
    const int wid  = tid >> 5;
    const int wr   = wid & 3;     // 16 q-rows per warp row
    const int wc   = wid >> 2;    // 0..1
    const int qq   = lane >> 2;   // 0..7
    const int kk   = lane & 3;    // 0..3

    const int q0 = blockIdx.x * BQ;
    const int h  = blockIdx.y;
    const int b  = blockIdx.z;
    const long base = (long)b * SEQ;
    const int  hoff = h * HDIM;

    // Q fragments: rows r0 = 16wr+qq, r1 = r0+8; scaled by 1/8; hi/lo planes.
    unsigned qh[8][4], ql[8][4];
    {
        const float* Q0 = &g_q[(base + q0 + 16 * wr + qq) * DIM + hoff];
        const float* Q1 = Q0 + 8 * DIM;
#pragma unroll
        for (int s = 0; s < 8; s++) {
            float v[4] = {Q0[8 * s + kk]     * 0.125f,
                          Q1[8 * s + kk]     * 0.125f,
                          Q0[8 * s + kk + 4] * 0.125f,
                          Q1[8 * s + kk + 4] * 0.125f};
#pragma unroll
            for (int j = 0; j < 4; j++) {
                unsigned hi = tf32_of(v[j]);
                qh[s][j] = hi;
                ql[s][j] = tf32_of(v[j] - __uint_as_float(hi));
            }
        }
    }

    if (tid < BQ) { m_s[tid] = -1e30f; l_s[tid] = 0.f; }

    float o[4][4];
#pragma unroll
    for (int u = 0; u < 4; u++)
#pragma unroll
        for (int r = 0; r < 4; r++) o[u][r] = 0.f;

    const int nkt = (q0 + BQ) / BK;
    for (int kt = 0; kt < nkt; kt++) {
        const int k0 = kt * BK;

        // Stage K (hi/lo tf32) and V (tf32) — coalesced gmem reads.
        {
            const int row  = tid >> 3;          // 0..31 (key)
            const int col0 = (tid & 7) * 8;     // head-dim base
            const float* ks = &g_k[(base + k0 + row) * DIM + hoff + col0];
            const float* vs = &g_v[(base + k0 + row) * DIM + hoff + col0];
#pragma unroll
            for (int i = 0; i < 8; i += 4) {
                float4 kv = *(const float4*)(ks + i);
                float4 vv = *(const float4*)(vs + i);
                float ka[4] = {kv.x, kv.y, kv.z, kv.w};
                float va[4] = {vv.x, vv.y, vv.z, vv.w};
#pragma unroll
                for (int j = 0; j < 4; j++) {
                    unsigned hi = tf32_of(ka[j]);
                    KsH[row][col0 + i + j] = hi;
                    KsL[row][col0 + i + j] = tf32_of(ka[j] - __uint_as_float(hi));
                    Vt[row][col0 + i + j]  = tf32_of(va[j]);
                }
            }
        }
        __syncthreads();

        // QK^T (3xTF32): warp computes S rows 16wr..+15, cols wc*16..+15.
        {
            float sacc[2][4];
#pragma unroll
            for (int u = 0; u < 2; u++)
#pragma unroll
                for (int r = 0; r < 4; r++) sacc[u][r] = 0.f;

#pragma unroll
            for (int s = 0; s < 8; s++) {
#pragma unroll
                for (int u = 0; u < 2; u++) {
                    const int n = wc * 16 + u * 8 + qq;   // key col
                    unsigned bh[2] = {KsH[n][8 * s + kk], KsH[n][8 * s + kk + 4]};
                    unsigned bl[2] = {KsL[n][8 * s + kk], KsL[n][8 * s + kk + 4]};
                    mma_tf32(sacc[u], qh[s], bh);
                    mma_tf32(sacc[u], qh[s], bl);
                    mma_tf32(sacc[u], ql[s], bh);
                }
            }

            // Write S with causal mask. c0,c1 -> row r0; c2,c3 -> row r1.
            const int r0 = 16 * wr + qq, r1 = r0 + 8;
#pragma unroll
            for (int u = 0; u < 2; u++) {
                const int colb = wc * 16 + u * 8 + 2 * kk;
#pragma unroll
                for (int j = 0; j < 2; j++) {
                    float v0 = sacc[u][j];
                    float v1 = sacc[u][2 + j];
                    if (k0 + colb + j > q0 + r0) v0 = -1e30f;
                    if (k0 + colb + j > q0 + r1) v1 = -1e30f;
                    Ss[r0][colb + j] = v0;
                    Ss[r1][colb + j] = v1;
                }
            }
        }
        __syncthreads();

        // Online softmax (verified): 2 lanes per row, shuffle combine.
        if (tid < BQ * 2) {
            const int row  = tid >> 1;
            const int cbeg = (tid & 1) * (BK / 2);
            const float mo = m_s[row];

            float mx = -1e30f;
#pragma unroll
            for (int c = 0; c < BK / 2; c++) mx = fmaxf(mx, Ss[row][cbeg + c]);
            mx = fmaxf(mx, __shfl_xor_sync(0xFFFFFFFFu, mx, 1));
            mx = fmaxf(mx, mo);

            float sum = 0.f;
#pragma unroll
            for (int c = 0; c < BK / 2; c++) {
                float p = __expf(Ss[row][cbeg + c] - mx);
                Ss[row][cbeg + c] = p;
                sum += p;
            }
            sum += __shfl_xor_sync(0xFFFFFFFFu, sum, 1);

            if ((tid & 1) == 0) {
                float a = __expf(mo - mx);
                m_s[row] = mx;
                l_s[row] = l_s[row] * a + sum;
                alf[row] = a;
            }
        }
        __syncthreads();

        // P·V: warp computes O rows 16wr..+15, cols wc*32..+31 (4 n-tiles).
        {
            const int r0 = 16 * wr + qq, r1 = r0 + 8;
            const float a0 = alf[r0], a1 = alf[r1];
#pragma unroll
            for (int u = 0; u < 4; u++) {
                o[u][0] *= a0; o[u][1] *= a0;
                o[u][2] *= a1; o[u][3] *= a1;
            }
#pragma unroll
            for (int s = 0; s < 4; s++) {             // 32 keys = 4 k8 steps
                unsigned pa[4];
                pa[0] = tf32_of(Ss[r0][8 * s + kk]);
                pa[1] = tf32_of(Ss[r1][8 * s + kk]);
                pa[2] = tf32_of(Ss[r0][8 * s + kk + 4]);
                pa[3] = tf32_of(Ss[r1][8 * s + kk + 4]);
#pragma unroll
                for (int u = 0; u < 4; u++) {
                    const int n = 32 * wc + 8 * u + qq;   // head-dim col
                    unsigned bv[2] = {Vt[8 * s + kk][n], Vt[8 * s + kk + 4][n]};
                    mma_tf32(o[u], pa, bv);
                }
            }
        }
        __syncthreads();
    }

    // Epilogue: divide by l, write g_att.
    {
        const int r0 = 16 * wr + qq, r1 = r0 + 8;
        const float i0 = 1.f / l_s[r0], i1 = 1.f / l_s[r1];
        float* O0 = &g_att[(base + q0 + r0) * DIM + hoff + 32 * wc];
        float* O1 = &g_att[(base + q0 + r1) * DIM + hoff + 32 * wc];
#pragma unroll
        for (int u = 0; u < 4; u++) {
            const int cb = 8 * u + 2 * kk;
            *(float2*)(O0 + cb) = make_float2(o[u][0] * i0, o[u][1] * i0);
            *(float2*)(O1 + cb) = make_float2(o[u][2] * i1, o[u][3] * i1);
        }
    }
}

// ---------------------------------------------------------------------------
extern "C" void kernel_launch(void* const* d_in, const int* in_sizes, int n_in,
                              void* d_out, int out_size)
{
    const float* x  = (const float*)d_in[0];
    const float* wq = (const float*)d_in[1];
    const float* wk = (const float*)d_in[2];
    const float* wv = (const float*)d_in[3];
    const float* wo = (const float*)d_in[4];
    float* out = (float*)d_out;

    dim3 gqkv(DIM / GT, MROWS / GT, 3);       // (8, 64, 3)
    qkv_gemm_kernel<<<gqkv, 256>>>(x, wq, wk, wv);

    dim3 gattn(SEQ / BQ, NHEAD, BATCH);        // (32, 16, 4)
    attn_kernel<<<gattn, 256>>>();

    dim3 gout(DIM / GT, MROWS / GT);           // (8, 64)
    out_gemm_kernel<<<gout, 256>>>(wo, out);
}

// round 16
// speedup vs baseline: 1.7903x; 1.0430x over previous
#include <cuda_runtime.h>
#include <cuda_bf16.h>

// ---------------------------------------------------------------------------
// CausalSelfAttention  (B=4, T=2048, DIM=1024, H=16, Dh=64)
//   1) QKV projections — 3xTF32 tensor-core GEMM, fragment-ready smem layout
//   2) causal flash attention — tensor-core (verified round-15 version)
//   3) output projection — same GEMM body
// Fragment-ready layout: smem holds hi/lo tf32 planes pre-permuted into
// m16n8k8 fragment order, so mainloop fragment loads are LDS.64 pairs
// (24 wide loads/warp-ktile vs 48 scalar). XOR swizzles keep staging STS
// at 2-way and fragment loads conflict-free.
// ---------------------------------------------------------------------------

#define BATCH 4
#define SEQ   2048
#define DIM   1024
#define NHEAD 16
#define HDIM  64
#define MROWS (BATCH * SEQ)   // 8192

__device__ float g_q[MROWS * DIM];
__device__ float g_k[MROWS * DIM];
__device__ float g_v[MROWS * DIM];
__device__ float g_att[MROWS * DIM];

#define GT 128
#define KT 8

__device__ __forceinline__ unsigned tf32_of(float x) {
    unsigned u;
    asm("cvt.rna.tf32.f32 %0, %1;" : "=r"(u) : "f"(x));
    return u;
}

__device__ __forceinline__ void mma_tf32(float c[4], const unsigned a[4],
                                         const unsigned b[2]) {
    asm volatile(
        "mma.sync.aligned.m16n8k8.row.col.f32.tf32.tf32.f32 "
        "{%0,%1,%2,%3}, {%4,%5,%6,%7}, {%8,%9}, {%0,%1,%2,%3};\n"
        : "+f"(c[0]), "+f"(c[1]), "+f"(c[2]), "+f"(c[3])
        : "r"(a[0]), "r"(a[1]), "r"(a[2]), "r"(a[3]),
          "r"(b[0]), "r"(b[1]));
}

// ---------------------------------------------------------------------------
// 3xTF32 GEMM with fragment-ready smem.
//   Af[buf][plane][khalf][t][pos][half]:
//     element A[m][k] (within 128x8 tile): t=m>>4, qq=m&7, half=(m>>3)&1,
//     kk=k&3, khalf=k>>2, pos=(qq*4+kk)^(2*khalf).
//     Loader (lane, regpair khalf) reads uint2 at pos=lane^(2*khalf)
//     -> {a[2*khalf], a[2*khalf+1]}.
//   Bf[buf][plane][ub][pos][khalf]:
//     element B[n][k]: ub=n>>3, qq=n&7, kk=k&3, khalf=k>>2,
//     pos=(qq*4+kk)^(2*(ub&1)). Loader reads uint2 at pos=lane^(2*(ub&1))
//     -> {b0,b1}.
// ---------------------------------------------------------------------------
__device__ __forceinline__ void gemm3tf32_body(
    const float* __restrict__ A, const float* __restrict__ B,
    float* __restrict__ C, int N, int K, int m0, int n0)
{
    __shared__ unsigned Af[2][2][2][8][32][2];   // 16 KB
    __shared__ unsigned Bf[2][2][16][32][2];     // 16 KB

    const int tid  = threadIdx.x;
    const int lane = tid & 31;
    const int wid  = tid >> 5;
    const int wm   = wid >> 2;   // warp row (64 rows)
    const int wn   = wid & 3;    // warp col (32 cols)

    const int lr = tid >> 1;          // staged row 0..127
    const int lc = (tid & 1) * 4;     // staged k offset 0 or 4
    const int st_t    = lr >> 4;
    const int st_qq   = lr & 7;
    const int st_half = (lr >> 3) & 1;
    const int st_kh   = lc >> 2;      // khalf for this thread's 4 elements
    const int st_ub   = lr >> 3;      // B col-group
    const int st_bx   = 2 * (st_ub & 1);

    float c[4][4][4];
#pragma unroll
    for (int t = 0; t < 4; t++)
#pragma unroll
        for (int u = 0; u < 4; u++)
#pragma unroll
            for (int r = 0; r < 4; r++) c[t][u][r] = 0.f;

    const float* Aptr = A + (long)(m0 + lr) * K + lc;
    const float* Bptr = B + (long)(n0 + lr) * K + lc;

    // Stage one K-tile into buffer `bf` (decomp to hi/lo tf32, frag order).
    auto stage = [&](int bf, float4 av, float4 bv) {
        float aa[4] = {av.x, av.y, av.z, av.w};
        float bb[4] = {bv.x, bv.y, bv.z, bv.w};
#pragma unroll
        for (int j = 0; j < 4; j++) {
            unsigned ahi = tf32_of(aa[j]);
            unsigned alo = tf32_of(aa[j] - __uint_as_float(ahi));
            const int pa = (st_qq * 4 + j) ^ (2 * st_kh);
            Af[bf][0][st_kh][st_t][pa][st_half] = ahi;
            Af[bf][1][st_kh][st_t][pa][st_half] = alo;

            unsigned bhi = tf32_of(bb[j]);
            unsigned blo = tf32_of(bb[j] - __uint_as_float(bhi));
            const int pb = (st_qq * 4 + j) ^ st_bx;
            Bf[bf][0][st_ub][pb][st_kh] = bhi;
            Bf[bf][1][st_ub][pb][st_kh] = blo;
        }
    };

    {
        float4 av = *(const float4*)(Aptr);
        float4 bv = *(const float4*)(Bptr);
        stage(0, av, bv);
    }
    __syncthreads();

    const int laneA0 = lane;            // pos for regpair 0
    const int laneA1 = lane ^ 2;        // pos for regpair 1 (khalf XOR)

    int buf = 0;
    for (int kt = 0; kt < K; kt += KT) {
        const bool have_next = (kt + KT) < K;
        float4 av, bv;
        if (have_next) {
            av = *(const float4*)(Aptr + kt + KT);
            bv = *(const float4*)(Bptr + kt + KT);
        }

        // Fragment loads: wide LDS.64 pairs.
        unsigned ah[4][4], al[4][4], bh[4][2], bl[4][2];
#pragma unroll
        for (int t = 0; t < 4; t++) {
            const int tt = wm * 4 + t;
            uint2 h0 = *(const uint2*)&Af[buf][0][0][tt][laneA0][0];
            uint2 h1 = *(const uint2*)&Af[buf][0][1][tt][laneA1][0];
            uint2 l0 = *(const uint2*)&Af[buf][1][0][tt][laneA0][0];
            uint2 l1 = *(const uint2*)&Af[buf][1][1][tt][laneA1][0];
            ah[t][0] = h0.x; ah[t][1] = h0.y; ah[t][2] = h1.x; ah[t][3] = h1.y;
            al[t][0] = l0.x; al[t][1] = l0.y; al[t][2] = l1.x; al[t][3] = l1.y;
        }
#pragma unroll
        for (int u = 0; u < 4; u++) {
            const int ub = wn * 4 + u;
            const int lb = lane ^ (2 * (ub & 1));
            uint2 h = *(const uint2*)&Bf[buf][0][ub][lb][0];
            uint2 l = *(const uint2*)&Bf[buf][1][ub][lb][0];
            bh[u][0] = h.x; bh[u][1] = h.y;
            bl[u][0] = l.x; bl[u][1] = l.y;
        }

        // 3xTF32: hi*hi + hi*lo + lo*hi
#pragma unroll
        for (int t = 0; t < 4; t++)
#pragma unroll
            for (int u = 0; u < 4; u++) {
                mma_tf32(c[t][u], ah[t], bh[u]);
                mma_tf32(c[t][u], ah[t], bl[u]);
                mma_tf32(c[t][u], al[t], bh[u]);
            }

        if (have_next) {
            const int nb = buf ^ 1;
            stage(nb, av, bv);
            __syncthreads();
            buf = nb;
        }
    }

    // Epilogue (identical mapping to verified version).
    const int qq = lane >> 2;
    const int p2 = (lane & 3) * 2;
#pragma unroll
    for (int t = 0; t < 4; t++) {
        const long r = m0 + wm * 64 + t * 16 + qq;
#pragma unroll
        for (int u = 0; u < 4; u++) {
            const int cc = n0 + wn * 32 + u * 8 + p2;
            *(float2*)(&C[r * N + cc])       = make_float2(c[t][u][0], c[t][u][1]);
            *(float2*)(&C[(r + 8) * N + cc]) = make_float2(c[t][u][2], c[t][u][3]);
        }
    }
}

__global__ __launch_bounds__(256) void qkv_gemm_kernel(
    const float* __restrict__ x,
    const float* __restrict__ wq,
    const float* __restrict__ wk,
    const float* __restrict__ wv)
{
    const int z = blockIdx.z;
    const float* W = (z == 0) ? wq : (z == 1) ? wk : wv;
    float* dst     = (z == 0) ? g_q : (z == 1) ? g_k : g_v;
    gemm3tf32_body(x, W, dst, DIM, DIM, blockIdx.y * GT, blockIdx.x * GT);
}

__global__ __launch_bounds__(256) void out_gemm_kernel(
    const float* __restrict__ wo, float* __restrict__ out)
{
    gemm3tf32_body(g_att, wo, out, DIM, DIM, blockIdx.y * GT, blockIdx.x * GT);
}

// ---------------------------------------------------------------------------
// Tensor-core flash attention (causal) — byte-identical to verified round-15.
// ---------------------------------------------------------------------------
#define BQ 64
#define BK 32

__global__ __launch_bounds__(256) void attn_kernel()
{
    __shared__ unsigned KsH[BK][68];
    __shared__ unsigned KsL[BK][68];
    __shared__ unsigned Vt[BK][68];
    __shared__ float Ss[BQ][36];
    __shared__ float m_s[BQ], l_s[BQ], alf[BQ];

    const int tid  = threadIdx.x;
    const int lane = tid & 31;
    const int wid  = tid >> 5;
    const int wr   = wid & 3;
    const int wc   = wid >> 2;
    const int qq   = lane >> 2;
    const int kk   = lane & 3;

    const int q0 = blockIdx.x * BQ;
    const int h  = blockIdx.y;
    const int b  = blockIdx.z;
    const long base = (long)b * SEQ;
    const int  hoff = h * HDIM;

    unsigned qh[8][4], ql[8][4];
    {
        const float* Q0 = &g_q[(base + q0 + 16 * wr + qq) * DIM + hoff];
        const float* Q1 = Q0 + 8 * DIM;
#pragma unroll
        for (int s = 0; s < 8; s++) {
            float v[4] = {Q0[8 * s + kk]     * 0.125f,
                          Q1[8 * s + kk]     * 0.125f,
                          Q0[8 * s + kk + 4] * 0.125f,
                          Q1[8 * s + kk + 4] * 0.125f};
#pragma unroll
            for (int j = 0; j < 4; j++) {
                unsigned hi = tf32_of(v[j]);
                qh[s][j] = hi;
                ql[s][j] = tf32_of(v[j] - __uint_as_float(hi));
            }
        }
    }

    if (tid < BQ) { m_s[tid] = -1e30f; l_s[tid] = 0.f; }

    float o[4][4];
#pragma unroll
    for (int u = 0; u < 4; u++)
#pragma unroll
        for (int r = 0; r < 4; r++) o[u][r] = 0.f;

    const int nkt = (q0 + BQ) / BK;
    for (int kt = 0; kt < nkt; kt++) {
        const int k0 = kt * BK;

        {
            const int row  = tid >> 3;
            const int col0 = (tid & 7) * 8;
            const float* ks = &g_k[(base + k0 + row) * DIM + hoff + col0];
            const float* vs = &g_v[(base + k0 + row) * DIM + hoff + col0];
#pragma unroll
            for (int i = 0; i < 8; i += 4) {
                float4 kv = *(const float4*)(ks + i);
                float4 vv = *(const float4*)(vs + i);
                float ka[4] = {kv.x, kv.y, kv.z, kv.w};
                float va[4] = {vv.x, vv.y, vv.z, vv.w};
#pragma unroll
                for (int j = 0; j < 4; j++) {
                    unsigned hi = tf32_of(ka[j]);
                    KsH[row][col0 + i + j] = hi;
                    KsL[row][col0 + i + j] = tf32_of(ka[j] - __uint_as_float(hi));
                    Vt[row][col0 + i + j]  = tf32_of(va[j]);
                }
            }
        }
        __syncthreads();

        {
            float sacc[2][4];
#pragma unroll
            for (int u = 0; u < 2; u++)
#pragma unroll
                for (int r = 0; r < 4; r++) sacc[u][r] = 0.f;

#pragma unroll
            for (int s = 0; s < 8; s++) {
#pragma unroll
                for (int u = 0; u < 2; u++) {
                    const int n = wc * 16 + u * 8 + qq;
                    unsigned bh[2] = {KsH[n][8 * s + kk], KsH[n][8 * s + kk + 4]};
                    unsigned bl[2] = {KsL[n][8 * s + kk], KsL[n][8 * s + kk + 4]};
                    mma_tf32(sacc[u], qh[s], bh);
                    mma_tf32(sacc[u], qh[s], bl);
                    mma_tf32(sacc[u], ql[s], bh);
                }
            }

            const int r0 = 16 * wr + qq, r1 = r0 + 8;
#pragma unroll
            for (int u = 0; u < 2; u++) {
                const int colb = wc * 16 + u * 8 + 2 * kk;
#pragma unroll
                for (int j = 0; j < 2; j++) {
                    float v0 = sacc[u][j];
                    float v1 = sacc[u][2 + j];
                    if (k0 + colb + j > q0 + r0) v0 = -1e30f;
                    if (k0 + colb + j > q0 + r1) v1 = -1e30f;
                    Ss[r0][colb + j] = v0;
                    Ss[r1][colb + j] = v1;
                }
            }
        }
        __syncthreads();

        if (tid < BQ * 2) {
            const int row  = tid >> 1;
            const int cbeg = (tid & 1) * (BK / 2);
            const float mo = m_s[row];

            float mx = -1e30f;
#pragma unroll
            for (int c = 0; c < BK / 2; c++) mx = fmaxf(mx, Ss[row][cbeg + c]);
            mx = fmaxf(mx, __shfl_xor_sync(0xFFFFFFFFu, mx, 1));
            mx = fmaxf(mx, mo);

            float sum = 0.f;
#pragma unroll
            for (int c = 0; c < BK / 2; c++) {
                float p = __expf(Ss[row][cbeg + c] - mx);
                Ss[row][cbeg + c] = p;
                sum += p;
            }
            sum += __shfl_xor_sync(0xFFFFFFFFu, sum, 1);

            if ((tid & 1) == 0) {
                float a = __expf(mo - mx);
                m_s[row] = mx;
                l_s[row] = l_s[row] * a + sum;
                alf[row] = a;
            }
        }
        __syncthreads();

        {
            const int r0 = 16 * wr + qq, r1 = r0 + 8;
            const float a0 = alf[r0], a1 = alf[r1];
#pragma unroll
            for (int u = 0; u < 4; u++) {
                o[u][0] *= a0; o[u][1] *= a0;
                o[u][2] *= a1; o[u][3] *= a1;
            }
#pragma unroll
            for (int s = 0; s < 4; s++) {
                unsigned pa[4];
                pa[0] = tf32_of(Ss[r0][8 * s + kk]);
                pa[1] = tf32_of(Ss[r1][8 * s + kk]);
                pa[2] = tf32_of(Ss[r0][8 * s + kk + 4]);
                pa[3] = tf32_of(Ss[r1][8 * s + kk + 4]);
#pragma unroll
                for (int u = 0; u < 4; u++) {
                    const int n = 32 * wc + 8 * u + qq;
                    unsigned bv[2] = {Vt[8 * s + kk][n], Vt[8 * s + kk + 4][n]};
                    mma_tf32(o[u], pa, bv);
                }
            }
        }
        __syncthreads();
    }

    {
        const int r0 = 16 * wr + qq, r1 = r0 + 8;
        const float i0 = 1.f / l_s[r0], i1 = 1.f / l_s[r1];
        float* O0 = &g_att[(base + q0 + r0) * DIM + hoff + 32 * wc];
        float* O1 = &g_att[(base + q0 + r1) * DIM + hoff + 32 * wc];
#pragma unroll
        for (int u = 0; u < 4; u++) {
            const int cb = 8 * u + 2 * kk;
            *(float2*)(O0 + cb) = make_float2(o[u][0] * i0, o[u][1] * i0);
            *(float2*)(O1 + cb) = make_float2(o[u][2] * i1, o[u][3] * i1);
        }
    }
}

// ---------------------------------------------------------------------------
extern "C" void kernel_launch(void* const* d_in, const int* in_sizes, int n_in,
                              void* d_out, int out_size)
{
    const float* x  = (const float*)d_in[0];
    const float* wq = (const float*)d_in[1];
    const float* wk = (const float*)d_in[2];
    const float* wv = (const float*)d_in[3];
    const float* wo = (const float*)d_in[4];
    float* out = (float*)d_out;

    dim3 gqkv(DIM / GT, MROWS / GT, 3);       // (8, 64, 3)
    qkv_gemm_kernel<<<gqkv, 256>>>(x, wq, wk, wv);

    dim3 gattn(SEQ / BQ, NHEAD, BATCH);        // (32, 16, 4)
    attn_kernel<<<gattn, 256>>>();

    dim3 gout(DIM / GT, MROWS / GT);           // (8, 64)
    out_gemm_kernel<<<gout, 256>>>(wo, out);
}